// round 12
// baseline (speedup 1.0000x reference)
#include <cuda_runtime.h>

#define NBATCH 32
#define NSAMP  49152
#define FRAME  2048
#define NFRAME 24
#define NBAND  16
#define CSIZE  8        // CTAs per cluster (one cluster per batch)
#define CSAMP  6144     // samples per CTA
#define CFRAME 3        // frames per CTA
#define TPB    384      // 12 warps
#define NW     12
#define HSEG   8        // samples per packed half (thread owns 16 samples)
#define ROWF   18       // floats per thread row (16 data + 2 pad; odd 8B count -> conflict-free LDS.64)
#define CSTRIDE 12

typedef unsigned long long ull;

// ---------- packed f32x2 helpers ----------
__device__ __forceinline__ ull pk(float lo, float hi) {
    ull r; asm("mov.b64 %0, {%1, %2};" : "=l"(r) : "f"(lo), "f"(hi)); return r;
}
__device__ __forceinline__ float2 upk(ull v) {
    float2 r; asm("mov.b64 {%0, %1}, %2;" : "=f"(r.x), "=f"(r.y) : "l"(v)); return r;
}
__device__ __forceinline__ ull fma2(ull a, ull b, ull c) {
    ull r; asm("fma.rn.f32x2 %0, %1, %2, %3;" : "=l"(r) : "l"(a), "l"(b), "l"(c)); return r;
}
__device__ __forceinline__ ull mul2(ull a, ull b) {
    ull r; asm("mul.rn.f32x2 %0, %1, %2;" : "=l"(r) : "l"(a), "l"(b)); return r;
}
__device__ __forceinline__ unsigned smem_u32(const void* p) {
    unsigned r;
    asm("{ .reg .u64 t; cvta.to.shared.u64 t, %1; cvt.u32.u64 %0, t; }" : "=r"(r) : "l"(p));
    return r;
}

// smem float layout offsets
#define OFF_CSM   (TPB * ROWF)                       // 6912 floats; 16B aligned
#define OFF_WAGG  (OFF_CSM + NBAND * CFRAME * CSTRIDE)
#define OFF_MBOX  (OFF_WAGG + NW * 6)                // [2][6] double-buffered
#define OFF_PEER  (OFF_MBOX + 12)                    // [(CSIZE-1)*6] = 42
#define OFF_IG    (OFF_PEER + (CSIZE - 1) * 6)       // [CFRAME]
#define OFF_OG    (OFF_IG + CFRAME)                  // [CFRAME]
#define SMEM_FLOATS (OFF_OG + CFRAME)

// physical index inside tile for CTA-local sample i (16 samples/thread, 2 halves of 8)
__device__ __forceinline__ int phys(int i) {
    int seg = i >> 4, loc = i & 15;
    return seg * ROWF + 2 * (loc & 7) + (loc >> 3);
}

__global__ __launch_bounds__(TPB, 2) __cluster_dims__(CSIZE, 1, 1)
void filter_kernel(const float* __restrict__ audio,
                   const float* __restrict__ params,
                   float* __restrict__ out) {
    extern __shared__ float smem[];
    float* xs      = smem;
    float* csm     = smem + OFF_CSM;
    float* warpAgg = smem + OFF_WAGG;
    float* mbox    = smem + OFF_MBOX;
    float* peerAgg = smem + OFF_PEER;
    float* ig_s    = smem + OFF_IG;
    float* og_s    = smem + OFF_OG;

    const int rank = blockIdx.x & (CSIZE - 1);
    const int b    = blockIdx.x >> 3;
    const int t    = threadIdx.x;
    const int w    = t >> 5;
    const int lane = t & 31;
    const int gbase = rank * CSAMP;
    const float* ab = audio + (size_t)b * NSAMP;
    const float* P  = params + (size_t)b * 50 * NFRAME;

    // --- broadband gains for this CTA's frames (needed by fill) ---
    if (t < CFRAME) {
        int f = rank * CFRAME + t;
        ig_s[t] = exp10f(3.0f * P[48 * NFRAME + f] - 3.0f);
        og_s[t] = exp10f(3.0f * P[49 * NFRAME + f] - 3.0f);
    }
    __syncthreads();

    // --- coefficient computation (threads 0..NBAND*CFRAME-1; fp64, once),
    //     overlapped with DRAM-latency-bound tile fill ---
    if (t < NBAND * CFRAME) {
        int band = t / CFRAME;
        int f    = rank * CFRAME + (t % CFRAME);
        float fn = P[(band * 3 + 0) * NFRAME + f];
        float gn = P[(band * 3 + 1) * NFRAME + f];
        float qn = P[(band * 3 + 2) * NFRAME + f];

        double Q = exp(-0.6931471805599453 + (double)qn * 3.4657359027997265);

        double flo, fhi; int type; // 0 hp, 1 lp, 2 lowshelf, 3 highshelf, 4 peak
        if      (band == 0)  { flo = 20.0;   fhi = 500.0;   type = 0; }
        else if (band == 15) { flo = 5000.0; fhi = 20000.0; type = 1; }
        else if (band == 1)  { flo = 50.0;   fhi = 16000.0; type = 2; }
        else if (band == 14) { flo = 50.0;   fhi = 16000.0; type = 3; }
        else                 { flo = 100.0;  fhi = 15000.0; type = 4; }

        double fc = exp(log(flo) + (double)fn * (log(fhi) - log(flo)));
        double g  = tan(3.141592653589793 * fc / 96000.0);
        g = fmin(fmax(g, 1e-6), 100.0);
        double gain = (double)(-24.0f + gn * 48.0f);

        double k, a1, a2, a3, m0, m1, m2;
        if (type <= 1) {
            k  = 1.0 / Q;
            a1 = 1.0 / (1.0 + g * (g + k));
            a2 = g * a1; a3 = g * a2;
            if (type == 0) { m0 = 1.0; m1 = -k; m2 = -1.0; }
            else           { m0 = 0.0; m1 = 0.0; m2 = 1.0; }
        } else if (type == 4) { // peak
            double A = exp10(gain / 40.0);
            k  = (gain >= 0.0) ? 1.0 / (Q * A) : A / Q;
            a1 = 1.0 / (1.0 + g * (g + k));
            a2 = g * a1; a3 = g * a2;
            m0 = 1.0; m1 = k * (A * A - 1.0); m2 = 0.0;
        } else {                // shelves
            double A  = exp10(gain / 40.0);
            double sA = sqrt(A);
            k = 1.0 / Q;
            double gs;
            if (type == 2) gs = (gain >= 0.0) ? g / sA : g * sA;
            else           gs = (gain >= 0.0) ? g * sA : g / sA;
            a1 = 1.0 / (1.0 + gs * (gs + k));
            a2 = gs * a1; a3 = gs * a2;
            if (type == 2) { m0 = 1.0;   m1 = k * (A - 1.0);       m2 = A * A - 1.0; }
            else           { m0 = A * A; m1 = k * (1.0 - A) * A;   m2 = 1.0 - A * A; }
        }
        double t22 = a2 * a2 + a3;
        float* c = &csm[t * CSTRIDE];
        c[0] = (float)(2.0 * a1 - 1.0);          // A11
        c[1] = (float)(-2.0 * a2);               // A12
        c[2] = (float)(2.0 * a1 * a2);           // A21
        c[3] = (float)(1.0 - 2.0 * t22);         // A22
        c[4] = (float)(2.0 * a2);                // C1
        c[5] = (float)(2.0 * t22);               // C2
        c[6] = (float)(m0 + m1 * a2 + m2 * t22); // E0
        c[7] = (float)(a1 * (m1 + m2 * a2));     // E1
        c[8] = (float)(-m1 * a2 + m2 * (1.0 - t22)); // E2
        c[9] = 0.f; c[10] = 0.f; c[11] = 0.f;
    }

    // fill tile, swizzled smem, coalesced gmem
    for (int i = t; i < CSAMP; i += TPB)
        xs[phys(i)] = ab[gbase + i] * ig_s[i >> 11];
    __syncthreads();

    ull* xr = (ull*)(xs + t * ROWF);   // 8B aligned (ROWF*4 = 72 = 8*9)

    for (int band = 0; band < NBAND; band++) {
        // thread's frame = (t*16)>>11 = t>>7 ; constant within a warp
        const float4* cp4 = (const float4*)&csm[(band * CFRAME + (t >> 7)) * CSTRIDE];
        float4 c0 = cp4[0], c1 = cp4[1], c2 = cp4[2];
        const float A11 = c0.x, A12 = c0.y, A21 = c0.z, A22 = c0.w;
        const float C1  = c1.x, C2  = c1.y;
        const float E0  = c1.z, E1  = c1.w, E2 = c2.x;
        const ull A11p = pk(A11, A11), A12p = pk(A12, A12);
        const ull A21p = pk(A21, A21), A22p = pk(A22, A22);
        const ull C1p  = pk(C1, C1),   C2p  = pk(C2, C2);
        const ull E0p  = pk(E0, E0),   E1p  = pk(E1, E1), E2p = pk(E2, E2);

        // pass 1 (packed): d-vector from zero state over both 8-sample halves
        ull d1p = 0, d2p = 0;
        #pragma unroll
        for (int j = 0; j < HSEG; j++) {
            ull xv = xr[j];
            ull n1 = fma2(A11p, d1p, fma2(A12p, d2p, mul2(C1p, xv)));
            ull n2 = fma2(A21p, d1p, fma2(A22p, d2p, mul2(C2p, xv)));
            d1p = n1; d2p = n2;
        }
        // M^8 by 3 squarings
        float P11 = A11, P12 = A12, P21 = A21, P22 = A22;
        #pragma unroll
        for (int sq = 0; sq < 3; sq++) {
            float tr  = P11 + P22;
            float od  = P12 * P21;
            float q11 = fmaf(P11, P11, od);
            float q12 = P12 * tr;
            float q21 = P21 * tr;
            float q22 = fmaf(P22, P22, od);
            P11 = q11; P12 = q12; P21 = q21; P22 = q22;
        }
        // thread aggregate over 16 samples: M = P^2, d = P*d_lo + d_hi
        float2 dv1 = upk(d1p), dv2 = upk(d2p);
        float G11, G12, G21, G22, gd1, gd2;
        {
            float tr = P11 + P22, od = P12 * P21;
            G11 = fmaf(P11, P11, od); G12 = P12 * tr;
            G21 = P21 * tr;           G22 = fmaf(P22, P22, od);
            gd1 = fmaf(P11, dv1.x, fmaf(P12, dv2.x, dv1.y));
            gd2 = fmaf(P21, dv1.x, fmaf(P22, dv2.x, dv2.y));
        }
        // warp inclusive scan
        #pragma unroll
        for (int off = 1; off < 32; off <<= 1) {
            float o11 = __shfl_up_sync(~0u, G11, off);
            float o12 = __shfl_up_sync(~0u, G12, off);
            float o21 = __shfl_up_sync(~0u, G21, off);
            float o22 = __shfl_up_sync(~0u, G22, off);
            float od1 = __shfl_up_sync(~0u, gd1, off);
            float od2 = __shfl_up_sync(~0u, gd2, off);
            if (lane >= off) {
                float n11 = fmaf(G11, o11, G12 * o21);
                float n12 = fmaf(G11, o12, G12 * o22);
                float n21 = fmaf(G21, o11, G22 * o21);
                float n22 = fmaf(G21, o12, G22 * o22);
                float nd1 = fmaf(G11, od1, fmaf(G12, od2, gd1));
                float nd2 = fmaf(G21, od1, fmaf(G22, od2, gd2));
                G11 = n11; G12 = n12; G21 = n21; G22 = n22; gd1 = nd1; gd2 = nd2;
            }
        }
        // lane-exclusive prefix
        float X11 = __shfl_up_sync(~0u, G11, 1);
        float X12 = __shfl_up_sync(~0u, G12, 1);
        float X21 = __shfl_up_sync(~0u, G21, 1);
        float X22 = __shfl_up_sync(~0u, G22, 1);
        float Xd1 = __shfl_up_sync(~0u, gd1, 1);
        float Xd2 = __shfl_up_sync(~0u, gd2, 1);
        if (lane == 0) { X11 = 1.f; X12 = 0.f; X21 = 0.f; X22 = 1.f; Xd1 = 0.f; Xd2 = 0.f; }
        if (lane == 31) {
            float* p = &warpAgg[w * 6];
            p[0] = G11; p[1] = G12; p[2] = G21; p[3] = G22; p[4] = gd1; p[5] = gd2;
        }
        __syncthreads();

        // block scan of NW warp aggregates (redundant per warp)
        float q11 = 1.f, q12 = 0.f, q21 = 0.f, q22 = 1.f, qd1 = 0.f, qd2 = 0.f;
        if (lane < NW) {
            const float* p = &warpAgg[lane * 6];
            q11 = p[0]; q12 = p[1]; q21 = p[2]; q22 = p[3]; qd1 = p[4]; qd2 = p[5];
        }
        #pragma unroll
        for (int off = 1; off < NW; off <<= 1) {
            float o11 = __shfl_up_sync(~0u, q11, off);
            float o12 = __shfl_up_sync(~0u, q12, off);
            float o21 = __shfl_up_sync(~0u, q21, off);
            float o22 = __shfl_up_sync(~0u, q22, off);
            float od1 = __shfl_up_sync(~0u, qd1, off);
            float od2 = __shfl_up_sync(~0u, qd2, off);
            if (lane >= off) {
                float n11 = fmaf(q11, o11, q12 * o21);
                float n12 = fmaf(q11, o12, q12 * o22);
                float n21 = fmaf(q21, o11, q22 * o21);
                float n22 = fmaf(q21, o12, q22 * o22);
                float nd1 = fmaf(q11, od1, fmaf(q12, od2, qd1));
                float nd2 = fmaf(q21, od1, fmaf(q22, od2, qd2));
                q11 = n11; q12 = n12; q21 = n21; q22 = n22; qd1 = nd1; qd2 = nd2;
            }
        }
        // warp-exclusive prefix affine (warps 0..w-1)
        float B11 = 1.f, B12 = 0.f, B21 = 0.f, B22 = 1.f, Bd1 = 0.f, Bd2 = 0.f;
        if (w > 0) {
            B11 = __shfl_sync(~0u, q11, w - 1);
            B12 = __shfl_sync(~0u, q12, w - 1);
            B21 = __shfl_sync(~0u, q21, w - 1);
            B22 = __shfl_sync(~0u, q22, w - 1);
            Bd1 = __shfl_sync(~0u, qd1, w - 1);
            Bd2 = __shfl_sync(~0u, qd2, w - 1);
        }
        // CTA total (lane NW-1 of warp 0) -> mailbox (parity-buffered)
        float* mb = &mbox[(band & 1) * 6];
        if (w == 0 && lane == NW - 1) {
            mb[0] = q11; mb[1] = q12; mb[2] = q21; mb[3] = q22; mb[4] = qd1; mb[5] = qd2;
        }
        // cluster barrier: publishes mailbox (arrive=release, wait=acquire);
        // also acts as a full block barrier.
        asm volatile("barrier.cluster.arrive.aligned;" ::: "memory");
        asm volatile("barrier.cluster.wait.aligned;"   ::: "memory");

        // stage earlier ranks' aggregates from peer DSMEM (threads 0..41)
        if (t < 6 * (CSIZE - 1)) {
            int k = t / 6, e = t % 6;
            if (k < rank) {
                unsigned la = smem_u32(&mb[e]);
                unsigned pa;
                asm("mapa.shared::cluster.u32 %0, %1, %2;" : "=r"(pa) : "r"(la), "r"(k));
                float v;
                asm("ld.shared::cluster.f32 %0, [%1];" : "=f"(v) : "r"(pa));
                peerAgg[t] = v;
            }
        }
        __syncthreads();

        // cluster-incoming state for this CTA (global init state is zero)
        float cs1 = 0.f, cs2 = 0.f;
        #pragma unroll
        for (int k = 0; k < CSIZE - 1; k++) {
            if (k < rank) {
                const float* p = &peerAgg[k * 6];
                float n1 = fmaf(p[0], cs1, fmaf(p[1], cs2, p[4]));
                float n2 = fmaf(p[2], cs1, fmaf(p[3], cs2, p[5]));
                cs1 = n1; cs2 = n2;
            }
        }
        // warp-incoming, lane-incoming, hi-half states
        float ws1 = fmaf(B11, cs1, fmaf(B12, cs2, Bd1));
        float ws2 = fmaf(B21, cs1, fmaf(B22, cs2, Bd2));
        float sl1 = fmaf(X11, ws1, fmaf(X12, ws2, Xd1));
        float sl2 = fmaf(X21, ws1, fmaf(X22, ws2, Xd2));
        float sh1 = fmaf(P11, sl1, fmaf(P12, sl2, dv1.x));
        float sh2 = fmaf(P21, sl1, fmaf(P22, sl2, dv2.x));
        ull s1p = pk(sl1, sh1), s2p = pk(sl2, sh2);

        // pass 2 (packed): replay, emit in place
        #pragma unroll
        for (int j = 0; j < HSEG; j++) {
            ull xv = xr[j];
            ull y  = fma2(E0p, xv, fma2(E1p, s1p, mul2(E2p, s2p)));
            ull n1 = fma2(A11p, s1p, fma2(A12p, s2p, mul2(C1p, xv)));
            ull n2 = fma2(A21p, s1p, fma2(A22p, s2p, mul2(C2p, xv)));
            xr[j] = y;
            s1p = n1; s2p = n2;
        }
    }
    __syncthreads();
    for (int i = t; i < CSAMP; i += TPB) {
        int gi = gbase + i;
        out[(size_t)b * NSAMP + gi] = xs[phys(i)] * og_s[i >> 11];
    }
}

extern "C" void kernel_launch(void* const* d_in, const int* in_sizes, int n_in,
                              void* d_out, int out_size) {
    const float* audio  = (const float*)d_in[0];
    const float* params = (const float*)d_in[1];
    if (n_in >= 2 && in_sizes[0] != NBATCH * NSAMP) { // robustness to input order
        const float* tmp = audio; audio = params; params = tmp;
    }
    float* out = (float*)d_out;

    size_t smem_bytes = (size_t)SMEM_FLOATS * sizeof(float);
    cudaFuncSetAttribute(filter_kernel,
                         cudaFuncAttributeMaxDynamicSharedMemorySize,
                         (int)smem_bytes);
    filter_kernel<<<NBATCH * CSIZE, TPB, smem_bytes>>>(audio, params, out);
}

// round 14
// speedup vs baseline: 1.1239x; 1.1239x over previous
#include <cuda_runtime.h>

#define NBATCH 32
#define NSAMP  49152
#define FRAME  2048
#define NFRAME 24
#define NBAND  16
#define CSIZE  4        // CTAs per cluster (one cluster per batch)
#define CSAMP  12288    // samples per CTA
#define CFRAME 6        // frames per CTA
#define TPB    384      // 12 warps
#define NW     12
#define HSEG   16       // samples per packed half (thread owns 32 samples)
#define ROWF   34       // floats per thread row (32 data + 2 pad; conflict-free LDS.64)
#define CSTRIDE 12

typedef unsigned long long ull;

// ---------- packed f32x2 helpers ----------
__device__ __forceinline__ ull pk(float lo, float hi) {
    ull r; asm("mov.b64 %0, {%1, %2};" : "=l"(r) : "f"(lo), "f"(hi)); return r;
}
__device__ __forceinline__ float2 upk(ull v) {
    float2 r; asm("mov.b64 {%0, %1}, %2;" : "=f"(r.x), "=f"(r.y) : "l"(v)); return r;
}
__device__ __forceinline__ ull fma2(ull a, ull b, ull c) {
    ull r; asm("fma.rn.f32x2 %0, %1, %2, %3;" : "=l"(r) : "l"(a), "l"(b), "l"(c)); return r;
}
__device__ __forceinline__ ull mul2(ull a, ull b) {
    ull r; asm("mul.rn.f32x2 %0, %1, %2;" : "=l"(r) : "l"(a), "l"(b)); return r;
}
__device__ __forceinline__ unsigned smem_u32(const void* p) {
    unsigned r;
    asm("{ .reg .u64 t; cvta.to.shared.u64 t, %1; cvt.u32.u64 %0, t; }" : "=r"(r) : "l"(p));
    return r;
}

// smem float layout offsets
#define OFF_CSM   (TPB * ROWF)                       // 13056
#define OFF_WAGG  (OFF_CSM + NBAND * CFRAME * CSTRIDE)   // +1152
#define OFF_TOT   (OFF_WAGG + NW * 6)                // per-band CTA totals [NBAND][6]
#define OFF_PEER  (OFF_TOT + NBAND * 6)              // [(CSIZE-1)*6] = 18
#define OFF_IG    (OFF_PEER + (CSIZE - 1) * 6)
#define OFF_OG    (OFF_IG + CFRAME)
#define OFF_MBAR  (OFF_OG + CFRAME)                  // even -> 8B aligned byte offset
#define SMEM_FLOATS (OFF_MBAR + NBAND * 2)

// physical index inside tile for CTA-local sample i (32 samples/thread, 2 halves of 16)
__device__ __forceinline__ int phys(int i) {
    int seg = i >> 5, loc = i & 31;
    return seg * ROWF + 2 * (loc & 15) + (loc >> 4);
}

__global__ __launch_bounds__(TPB, 1) __cluster_dims__(CSIZE, 1, 1)
void filter_kernel(const float* __restrict__ audio,
                   const float* __restrict__ params,
                   float* __restrict__ out) {
    extern __shared__ float smem[];
    float* xs      = smem;
    float* csm     = smem + OFF_CSM;
    float* warpAgg = smem + OFF_WAGG;
    float* totSlot = smem + OFF_TOT;
    float* peerAgg = smem + OFF_PEER;
    float* ig_s    = smem + OFF_IG;
    float* og_s    = smem + OFF_OG;
    ull*   mbar    = (ull*)(smem + OFF_MBAR);

    const int rank = blockIdx.x & (CSIZE - 1);
    const int b    = blockIdx.x >> 2;
    const int t    = threadIdx.x;
    const int w    = t >> 5;
    const int lane = t & 31;
    const int gbase = rank * CSAMP;
    const float* ab = audio + (size_t)b * NSAMP;
    const float* P  = params + (size_t)b * 50 * NFRAME;

    // --- mbar init: band-b mbar expects `rank` remote arrives (>=1 dummy for rank 0) ---
    if (t == 0) {
        int cnt = rank > 0 ? rank : 1;
        for (int i = 0; i < NBAND; i++) {
            unsigned a = smem_u32(&mbar[i]);
            asm volatile("mbarrier.init.shared.b64 [%0], %1;" :: "r"(a), "r"(cnt) : "memory");
        }
    }
    // --- broadband gains for this CTA's frames (needed by fill) ---
    if (t < CFRAME) {
        int f = rank * CFRAME + t;
        ig_s[t] = exp10f(3.0f * P[48 * NFRAME + f] - 3.0f);
        og_s[t] = exp10f(3.0f * P[49 * NFRAME + f] - 3.0f);
    }
    __syncthreads();
    // publish mbar inits cluster-wide before any remote arrive can land
    asm volatile("barrier.cluster.arrive.aligned;" ::: "memory");

    // --- coefficient computation (threads 0..95; fp64, once) overlapped with fill ---
    if (t < NBAND * CFRAME) {
        int band = t / CFRAME;
        int f    = rank * CFRAME + (t % CFRAME);
        float fn = P[(band * 3 + 0) * NFRAME + f];
        float gn = P[(band * 3 + 1) * NFRAME + f];
        float qn = P[(band * 3 + 2) * NFRAME + f];

        double Q = exp(-0.6931471805599453 + (double)qn * 3.4657359027997265);

        double flo, fhi; int type; // 0 hp, 1 lp, 2 lowshelf, 3 highshelf, 4 peak
        if      (band == 0)  { flo = 20.0;   fhi = 500.0;   type = 0; }
        else if (band == 15) { flo = 5000.0; fhi = 20000.0; type = 1; }
        else if (band == 1)  { flo = 50.0;   fhi = 16000.0; type = 2; }
        else if (band == 14) { flo = 50.0;   fhi = 16000.0; type = 3; }
        else                 { flo = 100.0;  fhi = 15000.0; type = 4; }

        double fc = exp(log(flo) + (double)fn * (log(fhi) - log(flo)));
        double g  = tan(3.141592653589793 * fc / 96000.0);
        g = fmin(fmax(g, 1e-6), 100.0);
        double gain = (double)(-24.0f + gn * 48.0f);

        double k, a1, a2, a3, m0, m1, m2;
        if (type <= 1) {
            k  = 1.0 / Q;
            a1 = 1.0 / (1.0 + g * (g + k));
            a2 = g * a1; a3 = g * a2;
            if (type == 0) { m0 = 1.0; m1 = -k; m2 = -1.0; }
            else           { m0 = 0.0; m1 = 0.0; m2 = 1.0; }
        } else if (type == 4) { // peak
            double A = exp10(gain / 40.0);
            k  = (gain >= 0.0) ? 1.0 / (Q * A) : A / Q;
            a1 = 1.0 / (1.0 + g * (g + k));
            a2 = g * a1; a3 = g * a2;
            m0 = 1.0; m1 = k * (A * A - 1.0); m2 = 0.0;
        } else {                // shelves
            double A  = exp10(gain / 40.0);
            double sA = sqrt(A);
            k = 1.0 / Q;
            double gs;
            if (type == 2) gs = (gain >= 0.0) ? g / sA : g * sA;
            else           gs = (gain >= 0.0) ? g * sA : g / sA;
            a1 = 1.0 / (1.0 + gs * (gs + k));
            a2 = gs * a1; a3 = gs * a2;
            if (type == 2) { m0 = 1.0;   m1 = k * (A - 1.0);       m2 = A * A - 1.0; }
            else           { m0 = A * A; m1 = k * (1.0 - A) * A;   m2 = 1.0 - A * A; }
        }
        double t22 = a2 * a2 + a3;
        float* c = &csm[t * CSTRIDE];
        c[0] = (float)(2.0 * a1 - 1.0);          // A11
        c[1] = (float)(-2.0 * a2);               // A12
        c[2] = (float)(2.0 * a1 * a2);           // A21
        c[3] = (float)(1.0 - 2.0 * t22);         // A22
        c[4] = (float)(2.0 * a2);                // C1
        c[5] = (float)(2.0 * t22);               // C2
        c[6] = (float)(m0 + m1 * a2 + m2 * t22); // E0
        c[7] = (float)(a1 * (m1 + m2 * a2));     // E1
        c[8] = (float)(-m1 * a2 + m2 * (1.0 - t22)); // E2
        c[9] = 0.f; c[10] = 0.f; c[11] = 0.f;
    }

    // fill tile, swizzled smem, coalesced gmem
    for (int i = t; i < CSAMP; i += TPB)
        xs[phys(i)] = ab[gbase + i] * ig_s[i >> 11];
    // complete the init-publication barrier (overlapped with coef+fill work)
    asm volatile("barrier.cluster.wait.aligned;" ::: "memory");
    __syncthreads();

    ull* xr = (ull*)(xs + t * ROWF);   // 8B aligned (ROWF*4 = 136 = 8*17)

    for (int band = 0; band < NBAND; band++) {
        const float4* cp4 = (const float4*)&csm[(band * CFRAME + (t >> 6)) * CSTRIDE];
        float4 c0 = cp4[0], c1 = cp4[1], c2 = cp4[2];
        const float A11 = c0.x, A12 = c0.y, A21 = c0.z, A22 = c0.w;
        const float C1  = c1.x, C2  = c1.y;
        const float E0  = c1.z, E1  = c1.w, E2 = c2.x;
        const ull A11p = pk(A11, A11), A12p = pk(A12, A12);
        const ull A21p = pk(A21, A21), A22p = pk(A22, A22);
        const ull C1p  = pk(C1, C1),   C2p  = pk(C2, C2);
        const ull E0p  = pk(E0, E0),   E1p  = pk(E1, E1), E2p = pk(E2, E2);

        // pass 1 (packed): d-vector from zero state over both 16-sample halves
        ull d1p = 0, d2p = 0;
        #pragma unroll
        for (int j = 0; j < HSEG; j++) {
            ull xv = xr[j];
            ull n1 = fma2(A11p, d1p, fma2(A12p, d2p, mul2(C1p, xv)));
            ull n2 = fma2(A21p, d1p, fma2(A22p, d2p, mul2(C2p, xv)));
            d1p = n1; d2p = n2;
        }
        // M^16 by 4 squarings
        float P11 = A11, P12 = A12, P21 = A21, P22 = A22;
        #pragma unroll
        for (int sq = 0; sq < 4; sq++) {
            float tr  = P11 + P22;
            float od  = P12 * P21;
            float q11 = fmaf(P11, P11, od);
            float q12 = P12 * tr;
            float q21 = P21 * tr;
            float q22 = fmaf(P22, P22, od);
            P11 = q11; P12 = q12; P21 = q21; P22 = q22;
        }
        // thread aggregate over 32 samples: M = P^2, d = P*d_lo + d_hi
        float2 dv1 = upk(d1p), dv2 = upk(d2p);
        float G11, G12, G21, G22, gd1, gd2;
        {
            float tr = P11 + P22, od = P12 * P21;
            G11 = fmaf(P11, P11, od); G12 = P12 * tr;
            G21 = P21 * tr;           G22 = fmaf(P22, P22, od);
            gd1 = fmaf(P11, dv1.x, fmaf(P12, dv2.x, dv1.y));
            gd2 = fmaf(P21, dv1.x, fmaf(P22, dv2.x, dv2.y));
        }
        // warp inclusive scan
        #pragma unroll
        for (int off = 1; off < 32; off <<= 1) {
            float o11 = __shfl_up_sync(~0u, G11, off);
            float o12 = __shfl_up_sync(~0u, G12, off);
            float o21 = __shfl_up_sync(~0u, G21, off);
            float o22 = __shfl_up_sync(~0u, G22, off);
            float od1 = __shfl_up_sync(~0u, gd1, off);
            float od2 = __shfl_up_sync(~0u, gd2, off);
            if (lane >= off) {
                float n11 = fmaf(G11, o11, G12 * o21);
                float n12 = fmaf(G11, o12, G12 * o22);
                float n21 = fmaf(G21, o11, G22 * o21);
                float n22 = fmaf(G21, o12, G22 * o22);
                float nd1 = fmaf(G11, od1, fmaf(G12, od2, gd1));
                float nd2 = fmaf(G21, od1, fmaf(G22, od2, gd2));
                G11 = n11; G12 = n12; G21 = n21; G22 = n22; gd1 = nd1; gd2 = nd2;
            }
        }
        // lane-exclusive prefix
        float X11 = __shfl_up_sync(~0u, G11, 1);
        float X12 = __shfl_up_sync(~0u, G12, 1);
        float X21 = __shfl_up_sync(~0u, G21, 1);
        float X22 = __shfl_up_sync(~0u, G22, 1);
        float Xd1 = __shfl_up_sync(~0u, gd1, 1);
        float Xd2 = __shfl_up_sync(~0u, gd2, 1);
        if (lane == 0) { X11 = 1.f; X12 = 0.f; X21 = 0.f; X22 = 1.f; Xd1 = 0.f; Xd2 = 0.f; }
        if (lane == 31) {
            float* p = &warpAgg[w * 6];
            p[0] = G11; p[1] = G12; p[2] = G21; p[3] = G22; p[4] = gd1; p[5] = gd2;
        }
        __syncthreads();

        // block scan of NW warp aggregates (redundant per warp)
        float q11 = 1.f, q12 = 0.f, q21 = 0.f, q22 = 1.f, qd1 = 0.f, qd2 = 0.f;
        if (lane < NW) {
            const float* p = &warpAgg[lane * 6];
            q11 = p[0]; q12 = p[1]; q21 = p[2]; q22 = p[3]; qd1 = p[4]; qd2 = p[5];
        }
        #pragma unroll
        for (int off = 1; off < NW; off <<= 1) {
            float o11 = __shfl_up_sync(~0u, q11, off);
            float o12 = __shfl_up_sync(~0u, q12, off);
            float o21 = __shfl_up_sync(~0u, q21, off);
            float o22 = __shfl_up_sync(~0u, q22, off);
            float od1 = __shfl_up_sync(~0u, qd1, off);
            float od2 = __shfl_up_sync(~0u, qd2, off);
            if (lane >= off) {
                float n11 = fmaf(q11, o11, q12 * o21);
                float n12 = fmaf(q11, o12, q12 * o22);
                float n21 = fmaf(q21, o11, q22 * o21);
                float n22 = fmaf(q21, o12, q22 * o22);
                float nd1 = fmaf(q11, od1, fmaf(q12, od2, qd1));
                float nd2 = fmaf(q21, od1, fmaf(q22, od2, qd2));
                q11 = n11; q12 = n12; q21 = n21; q22 = n22; qd1 = nd1; qd2 = nd2;
            }
        }
        // warp-exclusive prefix affine (warps 0..w-1)
        float B11 = 1.f, B12 = 0.f, B21 = 0.f, B22 = 1.f, Bd1 = 0.f, Bd2 = 0.f;
        if (w > 0) {
            B11 = __shfl_sync(~0u, q11, w - 1);
            B12 = __shfl_sync(~0u, q12, w - 1);
            B21 = __shfl_sync(~0u, q21, w - 1);
            B22 = __shfl_sync(~0u, q22, w - 1);
            Bd1 = __shfl_sync(~0u, qd1, w - 1);
            Bd2 = __shfl_sync(~0u, qd2, w - 1);
        }

        // ---- producer: publish CTA total for this band, signal higher ranks ----
        if (w == 0 && lane == NW - 1) {
            float* p = &totSlot[band * 6];
            p[0] = q11; p[1] = q12; p[2] = q21; p[3] = q22; p[4] = qd1; p[5] = qd2;
            unsigned la = smem_u32(&mbar[band]);
            #pragma unroll
            for (int peer = 0; peer < CSIZE; peer++) {
                if (peer > rank) {
                    unsigned pa;
                    asm("mapa.shared::cluster.u32 %0, %1, %2;" : "=r"(pa) : "r"(la), "r"(peer));
                    asm volatile("mbarrier.arrive.release.cluster.shared::cluster.b64 _, [%0];"
                                 :: "r"(pa) : "memory");
                }
            }
        }
        // ---- consumer (warp 0): wait for lower ranks, pull their totals ----
        if (w == 0 && rank > 0) {
            unsigned la = smem_u32(&mbar[band]);
            unsigned done;
            asm volatile(
                "{\n\t"
                ".reg .pred p;\n\t"
                "WAITLP_%=:\n\t"
                "mbarrier.try_wait.parity.acquire.cluster.shared::cta.b64 p, [%1], %2, 0x989680;\n\t"
                "@p bra.uni WDONE_%=;\n\t"
                "bra.uni WAITLP_%=;\n\t"
                "WDONE_%=:\n\t"
                "mov.u32 %0, 1;\n\t"
                "}"
                : "=r"(done) : "r"(la), "r"(0) : "memory");
            if (lane < 6 * (CSIZE - 1)) {
                int k = lane / 6, e = lane % 6;
                if (k < rank) {
                    unsigned sl = smem_u32(&totSlot[band * 6 + e]);
                    unsigned pa;
                    asm("mapa.shared::cluster.u32 %0, %1, %2;" : "=r"(pa) : "r"(sl), "r"(k));
                    float v;
                    asm volatile("ld.shared::cluster.f32 %0, [%1];" : "=f"(v) : "r"(pa) : "memory");
                    peerAgg[lane] = v;
                }
            }
        }
        __syncthreads();

        // cluster-incoming state for this CTA (global init state is zero)
        float cs1 = 0.f, cs2 = 0.f;
        #pragma unroll
        for (int k = 0; k < CSIZE - 1; k++) {
            if (k < rank) {
                const float* p = &peerAgg[k * 6];
                float n1 = fmaf(p[0], cs1, fmaf(p[1], cs2, p[4]));
                float n2 = fmaf(p[2], cs1, fmaf(p[3], cs2, p[5]));
                cs1 = n1; cs2 = n2;
            }
        }
        // warp-incoming, lane-incoming, hi-half states
        float ws1 = fmaf(B11, cs1, fmaf(B12, cs2, Bd1));
        float ws2 = fmaf(B21, cs1, fmaf(B22, cs2, Bd2));
        float sl1 = fmaf(X11, ws1, fmaf(X12, ws2, Xd1));
        float sl2 = fmaf(X21, ws1, fmaf(X22, ws2, Xd2));
        float sh1 = fmaf(P11, sl1, fmaf(P12, sl2, dv1.x));
        float sh2 = fmaf(P21, sl1, fmaf(P22, sl2, dv2.x));
        ull s1p = pk(sl1, sh1), s2p = pk(sl2, sh2);

        // pass 2 (packed): replay, emit in place
        #pragma unroll
        for (int j = 0; j < HSEG; j++) {
            ull xv = xr[j];
            ull y  = fma2(E0p, xv, fma2(E1p, s1p, mul2(E2p, s2p)));
            ull n1 = fma2(A11p, s1p, fma2(A12p, s2p, mul2(C1p, xv)));
            ull n2 = fma2(A21p, s1p, fma2(A22p, s2p, mul2(C2p, xv)));
            xr[j] = y;
            s1p = n1; s2p = n2;
        }
    }
    __syncthreads();
    for (int i = t; i < CSAMP; i += TPB) {
        int gi = gbase + i;
        out[(size_t)b * NSAMP + gi] = xs[phys(i)] * og_s[i >> 11];
    }
    // keep producers alive until all consumers pulled band-15 totals
    asm volatile("barrier.cluster.arrive.aligned;" ::: "memory");
    asm volatile("barrier.cluster.wait.aligned;"   ::: "memory");
}

extern "C" void kernel_launch(void* const* d_in, const int* in_sizes, int n_in,
                              void* d_out, int out_size) {
    const float* audio  = (const float*)d_in[0];
    const float* params = (const float*)d_in[1];
    if (n_in >= 2 && in_sizes[0] != NBATCH * NSAMP) { // robustness to input order
        const float* tmp = audio; audio = params; params = tmp;
    }
    float* out = (float*)d_out;

    size_t smem_bytes = (size_t)SMEM_FLOATS * sizeof(float);
    cudaFuncSetAttribute(filter_kernel,
                         cudaFuncAttributeMaxDynamicSharedMemorySize,
                         (int)smem_bytes);
    filter_kernel<<<NBATCH * CSIZE, TPB, smem_bytes>>>(audio, params, out);
}